// round 12
// baseline (speedup 1.0000x reference)
#include <cuda_runtime.h>
#include <cuda_fp16.h>
#include <math.h>
#include <stdint.h>

// Problem constants
#define Nn 50000
#define Ee 800000
#define Gg 1000
#define ND 128
#define HH 256
#define LL 4
#define PP 3

// ---------------- static scratch (no allocations allowed) ----------------
__device__ __half g_x16[Nn * ND];
__device__ __half g_h16[Nn * HH];            // hidden state, fp16, updated in place
__device__ __half g_m16[Nn * HH];
__device__ __half g_embWT[HH * ND];          // [n][k] = emb_W[k][n]
__device__ __half g_gcnWT[LL * HH * HH];     // [l][n][k] = gcn_W[l][k][n]
__device__ float  g_bnS[LL * HH];
__device__ float  g_bnT[LL * HH];
__device__ int    g_cnt[Nn];
__device__ int    g_fill[Nn];
__device__ float  g_dinv[Nn];
__device__ int    g_rowptr[Nn + 1];
__device__ int    g_colidx[Ee];
__device__ float  g_ew[Ee];
__device__ float  g_pool[Gg * HH];

// ---------------- graph preprocessing ----------------
__global__ void k_count(const int* __restrict__ ei)
{
    int e = blockIdx.x * blockDim.x + threadIdx.x;
    if (e < Ee) atomicAdd(&g_cnt[ei[Ee + e]], 1);
}

#define SCAN_CH 49   // ceil(50000/1024)
__global__ __launch_bounds__(1024) void k_scan()
{
    __shared__ int wsum[32];
    int t = threadIdx.x;
    int lane = t & 31, wrp = t >> 5;
    int base = t * SCAN_CH;

    int s = 0;
    #pragma unroll 7
    for (int i = 0; i < SCAN_CH; i++) {
        int idx = base + i;
        if (idx < Nn) {
            int c = g_cnt[idx];
            g_dinv[idx] = rsqrtf(1.0f + (float)c);
            s += c;
        }
    }
    int ps = s;
    #pragma unroll
    for (int d = 1; d < 32; d <<= 1) {
        int x = __shfl_up_sync(0xffffffffu, ps, d);
        if (lane >= d) ps += x;
    }
    if (lane == 31) wsum[wrp] = ps;
    __syncthreads();
    if (wrp == 0) {
        int x = wsum[lane];
        #pragma unroll
        for (int d = 1; d < 32; d <<= 1) {
            int y = __shfl_up_sync(0xffffffffu, x, d);
            if (lane >= d) x += y;
        }
        wsum[lane] = x;
    }
    __syncthreads();
    int off = ps - s + (wrp ? wsum[wrp - 1] : 0);

    #pragma unroll 7
    for (int i = 0; i < SCAN_CH; i++) {
        int idx = base + i;
        if (idx < Nn) {
            g_rowptr[idx] = off;
            off += g_cnt[idx];
        }
    }
    if (t == 0) g_rowptr[Nn] = Ee;
}

__global__ void k_fill(const int* __restrict__ ei)
{
    int e = blockIdx.x * blockDim.x + threadIdx.x;
    if (e >= Ee) return;
    int s = ei[e];
    int d = ei[Ee + e];
    int pos = g_rowptr[d] + atomicAdd(&g_fill[d], 1);
    g_colidx[pos] = s;
    g_ew[pos] = g_dinv[s] * g_dinv[d];
}

// ---------------- merged prep: x->fp16, weight transpose+cvt, BN fold ----------------
#define X4 (Nn * ND / 4)
#define WELEMS (HH*ND + LL*HH*HH)
__global__ __launch_bounds__(256) void k_prep(
    const float* __restrict__ x,
    const float* __restrict__ embW, const float* __restrict__ gcnW,
    const float* __restrict__ gcnb, const float* __restrict__ bng,
    const float* __restrict__ bnb, const float* __restrict__ bnm,
    const float* __restrict__ bnv)
{
    int t = blockIdx.x * blockDim.x + threadIdx.x;
    if (t < X4) {
        float4 v = ((const float4*)x)[t];
        __half2 a = __floats2half2_rn(v.x, v.y);
        __half2 b = __floats2half2_rn(v.z, v.w);
        uint2 o;
        o.x = *(uint32_t*)&a;
        o.y = *(uint32_t*)&b;
        ((uint2*)g_x16)[t] = o;
        return;
    }
    int u = t - X4;
    if (u < HH * ND) {
        int n = u / ND, k = u % ND;
        g_embWT[u] = __float2half_rn(embW[k * HH + n]);
    } else if (u < WELEMS) {
        int t2 = u - HH * ND;
        int l = t2 >> 16;
        int r = t2 & 65535;
        int n = r >> 8, k = r & 255;
        g_gcnWT[t2] = __float2half_rn(gcnW[l * HH * HH + k * HH + n]);
    } else if (u < WELEMS + LL * HH) {
        int i = u - WELEMS;
        float S = bng[i] * rsqrtf(bnv[i] + 1e-5f);
        g_bnS[i] = S;
        g_bnT[i] = (gcnb[i] - bnm[i]) * S + bnb[i];
    }
}
#define PREP_ITEMS (X4 + WELEMS + LL*HH)

// ---------------- fp16 tensor-core GEMM: 128x128, 3-stage, ldmatrix ----------------
__device__ __forceinline__ void cpa16(uint32_t dst, const void* src, int sz)
{
    asm volatile("cp.async.cg.shared.global [%0], [%1], 16, %2;\n"
                 :: "r"(dst), "l"(src), "r"(sz));
}
#define CP_COMMIT() asm volatile("cp.async.commit_group;\n" ::)
#define CP_WAIT(N)  asm volatile("cp.async.wait_group %0;\n" :: "n"(N))

__device__ __forceinline__ void ldm_x4(uint32_t& r0, uint32_t& r1,
                                       uint32_t& r2, uint32_t& r3, uint32_t a)
{
    asm volatile("ldmatrix.sync.aligned.m8n8.x4.shared.b16 {%0,%1,%2,%3}, [%4];"
                 : "=r"(r0), "=r"(r1), "=r"(r2), "=r"(r3) : "r"(a));
}
__device__ __forceinline__ void ldm_x2(uint32_t& r0, uint32_t& r1, uint32_t a)
{
    asm volatile("ldmatrix.sync.aligned.m8n8.x2.shared.b16 {%0,%1}, [%2];"
                 : "=r"(r0), "=r"(r1) : "r"(a));
}

#define STAGE_B 10240      // 128 rows * 40 halfs * 2B, per operand per stage
#define HGEMM_SMEM (6 * STAGE_B)

// RB: fuse bias + relu (embed layer); otherwise pure GEMM.
template<int K, bool RB>
__global__ __launch_bounds__(256, 2) void k_hgemm(
    const __half* __restrict__ A, const __half* __restrict__ BT,
    const float* __restrict__ bias, __half* __restrict__ C16, int M)
{
    constexpr int KT = K / 32;
    extern __shared__ __align__(16) __half sm[];

    int tid = threadIdx.x;
    int wid = tid >> 5, lane = tid & 31;
    int wm = wid & 1;
    int wn = wid >> 1;
    int g = lane >> 2;
    int q = lane & 3;
    int rowBase = blockIdx.x * 128;
    int colBase = blockIdx.y * 128;

    uint32_t sA = (uint32_t)__cvta_generic_to_shared(sm);
    uint32_t sB = sA + 3 * STAGE_B;

    int aRow = wm * 64 + (lane & 15);
    int aKof = (lane >> 4) << 3;
    int bRow = wn * 32 + (lane & 7);
    int bKof = ((lane >> 3) & 1) << 3;

    float c[4][4][4];
    #pragma unroll
    for (int i = 0; i < 4; i++)
        #pragma unroll
        for (int j = 0; j < 4; j++)
            #pragma unroll
            for (int r = 0; r < 4; r++) c[i][j][r] = 0.0f;

    int ldrow = tid >> 2;
    int ldc = tid & 3;

    auto stage = [&](int kt, int buf) {
        #pragma unroll
        for (int l = 0; l < 2; l++) {
            int row = ldrow + l * 64;
            int ga = rowBase + row;
            const __half* srcA = A + (size_t)ga * K + kt * 32 + ldc * 8;
            cpa16(sA + buf * STAGE_B + row * 80 + ldc * 16, srcA, (ga < M) ? 16 : 0);
            const __half* srcB = BT + (size_t)(colBase + row) * K + kt * 32 + ldc * 8;
            cpa16(sB + buf * STAGE_B + row * 80 + ldc * 16, srcB, 16);
        }
    };

    stage(0, 0);
    CP_COMMIT();
    if (KT > 1) { stage(1, 1); CP_COMMIT(); }

    for (int kt = 0; kt < KT; kt++) {
        if (kt + 1 < KT) { CP_WAIT(1); } else { CP_WAIT(0); }
        __syncthreads();
        if (kt + 2 < KT) { stage(kt + 2, (kt + 2) % 3); CP_COMMIT(); }

        uint32_t bA = sA + (kt % 3) * STAGE_B;
        uint32_t bB = sB + (kt % 3) * STAGE_B;

        #pragma unroll
        for (int ks = 0; ks < 32; ks += 16) {
            uint32_t a[4][4], b[4][2];
            #pragma unroll
            for (int mt = 0; mt < 4; mt++)
                ldm_x4(a[mt][0], a[mt][1], a[mt][2], a[mt][3],
                       bA + (aRow + mt * 16) * 80 + (ks + aKof) * 2);
            #pragma unroll
            for (int nt = 0; nt < 4; nt++)
                ldm_x2(b[nt][0], b[nt][1],
                       bB + (bRow + nt * 8) * 80 + (ks + bKof) * 2);
            #pragma unroll
            for (int mt = 0; mt < 4; mt++)
                #pragma unroll
                for (int nt = 0; nt < 4; nt++) {
                    asm volatile(
                        "mma.sync.aligned.m16n8k16.row.col.f32.f16.f16.f32 "
                        "{%0,%1,%2,%3}, {%4,%5,%6,%7}, {%8,%9}, {%0,%1,%2,%3};\n"
                        : "+f"(c[mt][nt][0]), "+f"(c[mt][nt][1]),
                          "+f"(c[mt][nt][2]), "+f"(c[mt][nt][3])
                        : "r"(a[mt][0]), "r"(a[mt][1]), "r"(a[mt][2]), "r"(a[mt][3]),
                          "r"(b[nt][0]), "r"(b[nt][1]));
                }
        }
    }

    // epilogue (fp16 output only)
    #pragma unroll
    for (int nt = 0; nt < 4; nt++) {
        int col = colBase + wn * 32 + nt * 8 + 2 * q;
        float b0 = 0.f, b1 = 0.f;
        if (RB) { b0 = bias[col]; b1 = bias[col + 1]; }
        #pragma unroll
        for (int mt = 0; mt < 4; mt++) {
            int r0 = rowBase + wm * 64 + mt * 16 + g;
            float v0 = c[mt][nt][0] + b0;
            float v1 = c[mt][nt][1] + b1;
            float v2 = c[mt][nt][2] + b0;
            float v3 = c[mt][nt][3] + b1;
            if (RB) {
                v0 = fmaxf(v0, 0.f); v1 = fmaxf(v1, 0.f);
                v2 = fmaxf(v2, 0.f); v3 = fmaxf(v3, 0.f);
            }
            if (r0 < M) {
                __half2 h = __floats2half2_rn(v0, v1);
                *(uint32_t*)&C16[(size_t)r0 * HH + col] = *(uint32_t*)&h;
            }
            if (r0 + 8 < M) {
                __half2 h = __floats2half2_rn(v2, v3);
                *(uint32_t*)&C16[(size_t)(r0 + 8) * HH + col] = *(uint32_t*)&h;
            }
        }
    }
}

// ---------------- aggregation: warp/node, software-pipelined 2-edge gather ----------------
__device__ __forceinline__ void acc_u4(float* acc, uint4 v, float w)
{
    const __half2* h = (const __half2*)&v;
    #pragma unroll
    for (int j = 0; j < 4; j++) {
        float2 f = __half22float2(h[j]);
        acc[2 * j]     = fmaf(f.x, w, acc[2 * j]);
        acc[2 * j + 1] = fmaf(f.y, w, acc[2 * j + 1]);
    }
}

__global__ __launch_bounds__(256) void k_agg(
    const __half* __restrict__ m16, __half* __restrict__ h16,
    const float* __restrict__ S, const float* __restrict__ T)
{
    int wid = threadIdx.x >> 5;
    int l = threadIdx.x & 31;
    int node = blockIdx.x * 8 + wid;
    if (node >= Nn) return;

    const uint4* mv = (const uint4*)m16;
    int beg = g_rowptr[node];
    int end = g_rowptr[node + 1];
    float di = g_dinv[node];
    float sn = di * di;

    float acc[8];
    {
        uint4 v = mv[(size_t)node * 32 + l];
        const __half2* h = (const __half2*)&v;
        #pragma unroll
        for (int j = 0; j < 4; j++) {
            float2 f = __half22float2(h[j]);
            acc[2 * j] = f.x * sn;
            acc[2 * j + 1] = f.y * sn;
        }
    }

    // software pipeline: indices for the current pair are loaded one
    // iteration ahead, so gather addresses are ready when issued, and the
    // two gathers per iteration are independent (MLP=2).
    int e = beg;
    int n2 = end - ((end - beg) & 1);   // paired region
    int s0, s1;
    float w0, w1;
    if (e < n2) {
        s0 = __ldg(&g_colidx[e]);     w0 = __ldg(&g_ew[e]);
        s1 = __ldg(&g_colidx[e + 1]); w1 = __ldg(&g_ew[e + 1]);
    }
    for (; e < n2; ) {
        uint4 v0 = mv[(size_t)s0 * 32 + l];
        uint4 v1 = mv[(size_t)s1 * 32 + l];
        int ns0 = 0, ns1 = 0;
        float nw0 = 0.f, nw1 = 0.f;
        if (e + 3 < n2) {
            ns0 = __ldg(&g_colidx[e + 2]); nw0 = __ldg(&g_ew[e + 2]);
            ns1 = __ldg(&g_colidx[e + 3]); nw1 = __ldg(&g_ew[e + 3]);
        }
        acc_u4(acc, v0, w0);
        acc_u4(acc, v1, w1);
        s0 = ns0; w0 = nw0; s1 = ns1; w1 = nw1;
        e += 2;
    }
    if (e < end) {   // odd remainder
        int s = __ldg(&g_colidx[e]);
        float w = __ldg(&g_ew[e]);
        acc_u4(acc, mv[(size_t)s * 32 + l], w);
    }

    float4 sv0 = ((const float4*)S)[l * 2];
    float4 sv1 = ((const float4*)S)[l * 2 + 1];
    float4 tv0 = ((const float4*)T)[l * 2];
    float4 tv1 = ((const float4*)T)[l * 2 + 1];

    float hi[8];
    {
        uint4 hv = ((const uint4*)h16)[(size_t)node * 32 + l];
        const __half2* h = (const __half2*)&hv;
        #pragma unroll
        for (int j = 0; j < 4; j++) {
            float2 f = __half22float2(h[j]);
            hi[2 * j] = f.x;
            hi[2 * j + 1] = f.y;
        }
    }

    float o[8];
    o[0] = fmaxf(fmaf(acc[0], sv0.x, tv0.x), 0.f) + hi[0];
    o[1] = fmaxf(fmaf(acc[1], sv0.y, tv0.y), 0.f) + hi[1];
    o[2] = fmaxf(fmaf(acc[2], sv0.z, tv0.z), 0.f) + hi[2];
    o[3] = fmaxf(fmaf(acc[3], sv0.w, tv0.w), 0.f) + hi[3];
    o[4] = fmaxf(fmaf(acc[4], sv1.x, tv1.x), 0.f) + hi[4];
    o[5] = fmaxf(fmaf(acc[5], sv1.y, tv1.y), 0.f) + hi[5];
    o[6] = fmaxf(fmaf(acc[6], sv1.z, tv1.z), 0.f) + hi[6];
    o[7] = fmaxf(fmaf(acc[7], sv1.w, tv1.w), 0.f) + hi[7];

    __half2 p0 = __floats2half2_rn(o[0], o[1]);
    __half2 p1 = __floats2half2_rn(o[2], o[3]);
    __half2 p2 = __floats2half2_rn(o[4], o[5]);
    __half2 p3 = __floats2half2_rn(o[6], o[7]);
    uint4 pk;
    pk.x = *(uint32_t*)&p0; pk.y = *(uint32_t*)&p1;
    pk.z = *(uint32_t*)&p2; pk.w = *(uint32_t*)&p3;
    ((uint4*)h16)[(size_t)node * 32 + l] = pk;
}

// ---------------- global mean pool per graph (fp16 h, fp32 accumulate) ----------------
__device__ __forceinline__ int lbound(const int* __restrict__ a, int n, int key)
{
    int lo = 0, hi = n;
    while (lo < hi) {
        int mid = (lo + hi) >> 1;
        if (a[mid] < key) lo = mid + 1; else hi = mid;
    }
    return lo;
}

__global__ __launch_bounds__(256) void k_pool(const __half* __restrict__ h,
                                              const int* __restrict__ batch)
{
    int g = blockIdx.x;
    int c = threadIdx.x;
    int s = lbound(batch, Nn, g);
    int e = lbound(batch, Nn, g + 1);
    float acc = 0.0f;
    for (int n = s; n < e; n++) acc += __half2float(h[(size_t)n * HH + c]);
    float cnt = (float)(e - s);
    g_pool[g * HH + c] = acc / fmaxf(cnt, 1.0f);
}

// ---------------- property-head MLPs: 8 graphs per block (W reuse) ----------------
#define GPG 8
__global__ __launch_bounds__(128) void k_heads(
    const float* __restrict__ h1W, const float* __restrict__ h1b,
    const float* __restrict__ h2W, const float* __restrict__ h2b,
    const float* __restrict__ h3W, const float* __restrict__ h3b,
    float* __restrict__ out)
{
    int gbase = blockIdx.x * GPG;
    int p = blockIdx.y;
    __shared__ float gs[GPG][HH];
    __shared__ float z1[GPG][128];
    __shared__ float z2[GPG][64];
    int t = threadIdx.x;

    for (int i = t; i < GPG * HH; i += 128) {
        int gg = i >> 8, c = i & 255;
        int g = gbase + gg;
        gs[gg][c] = (g < Gg) ? g_pool[g * HH + c] : 0.0f;
    }
    __syncthreads();

    {   // layer 1: 256 -> 128
        const float* W1 = h1W + (size_t)p * HH * 128;
        float acc[GPG];
        #pragma unroll
        for (int gg = 0; gg < GPG; gg++) acc[gg] = h1b[p * 128 + t];
        #pragma unroll 4
        for (int k = 0; k < HH; k++) {
            float w = W1[k * 128 + t];
            #pragma unroll
            for (int gg = 0; gg < GPG; gg++)
                acc[gg] = fmaf(gs[gg][k], w, acc[gg]);
        }
        #pragma unroll
        for (int gg = 0; gg < GPG; gg++) z1[gg][t] = fmaxf(acc[gg], 0.0f);
    }
    __syncthreads();

    if (t < 64) {   // layer 2: 128 -> 64
        const float* W2 = h2W + (size_t)p * 128 * 64;
        float acc[GPG];
        #pragma unroll
        for (int gg = 0; gg < GPG; gg++) acc[gg] = h2b[p * 64 + t];
        #pragma unroll 4
        for (int k = 0; k < 128; k++) {
            float w = W2[k * 64 + t];
            #pragma unroll
            for (int gg = 0; gg < GPG; gg++)
                acc[gg] = fmaf(z1[gg][k], w, acc[gg]);
        }
        #pragma unroll
        for (int gg = 0; gg < GPG; gg++) z2[gg][t] = fmaxf(acc[gg], 0.0f);
    }
    __syncthreads();

    if (t < 32) {   // layer 3: 64 -> 1, warp-reduce per graph
        const float* W3 = h3W + p * 64;
        float w0 = W3[t], w1 = W3[t + 32];
        #pragma unroll
        for (int gg = 0; gg < GPG; gg++) {
            float a3 = z2[gg][t] * w0 + z2[gg][t + 32] * w1;
            #pragma unroll
            for (int o = 16; o > 0; o >>= 1)
                a3 += __shfl_down_sync(0xffffffffu, a3, o);
            if (t == 0 && gbase + gg < Gg)
                out[(gbase + gg) * PP + p] = a3 + h3b[p];
        }
    }
}

// ---------------- launch ----------------
extern "C" void kernel_launch(void* const* d_in, const int* in_sizes, int n_in,
                              void* d_out, int out_size)
{
    const float* x     = (const float*)d_in[0];
    const int*   ei    = (const int*)d_in[1];
    const int*   batch = (const int*)d_in[2];
    const float* embW  = (const float*)d_in[3];
    const float* embb  = (const float*)d_in[4];
    const float* gcnW  = (const float*)d_in[5];
    const float* gcnb  = (const float*)d_in[6];
    const float* bng   = (const float*)d_in[7];
    const float* bnb   = (const float*)d_in[8];
    const float* bnm   = (const float*)d_in[9];
    const float* bnv   = (const float*)d_in[10];
    const float* h1W   = (const float*)d_in[11];
    const float* h1b   = (const float*)d_in[12];
    const float* h2W   = (const float*)d_in[13];
    const float* h2b   = (const float*)d_in[14];
    const float* h3W   = (const float*)d_in[15];
    const float* h3b   = (const float*)d_in[16];
    float* out = (float*)d_out;

    void *pX16_, *pH16_, *pM16_, *pEWT_, *pGWT_, *pS_, *pT_, *pCnt_, *pFill_;
    cudaGetSymbolAddress(&pX16_, g_x16);
    cudaGetSymbolAddress(&pH16_, g_h16);
    cudaGetSymbolAddress(&pM16_, g_m16);
    cudaGetSymbolAddress(&pEWT_, g_embWT);
    cudaGetSymbolAddress(&pGWT_, g_gcnWT);
    cudaGetSymbolAddress(&pS_, g_bnS);
    cudaGetSymbolAddress(&pT_, g_bnT);
    cudaGetSymbolAddress(&pCnt_, g_cnt);
    cudaGetSymbolAddress(&pFill_, g_fill);
    __half* x16 = (__half*)pX16_;
    __half* h16 = (__half*)pH16_;
    __half* m16 = (__half*)pM16_;
    __half* eWT = (__half*)pEWT_;
    __half* gWT = (__half*)pGWT_;
    float*  bnS = (float*)pS_;
    float*  bnT = (float*)pT_;

    cudaFuncSetAttribute(k_hgemm<ND, true>, cudaFuncAttributeMaxDynamicSharedMemorySize, HGEMM_SMEM);
    cudaFuncSetAttribute(k_hgemm<HH, false>, cudaFuncAttributeMaxDynamicSharedMemorySize, HGEMM_SMEM);

    dim3 ggrid((Nn + 127) / 128, 2);

    // memsets (graph memset nodes)
    cudaMemsetAsync(pCnt_, 0, Nn * sizeof(int));
    cudaMemsetAsync(pFill_, 0, Nn * sizeof(int));

    k_count<<<(Ee + 255) / 256, 256>>>(ei);
    k_scan<<<1, 1024>>>();
    k_prep<<<(PREP_ITEMS + 255) / 256, 256>>>(x, embW, gcnW, gcnb,
                                              bng, bnb, bnm, bnv);
    k_hgemm<ND, true><<<ggrid, 256, HGEMM_SMEM>>>(x16, eWT, embb, h16, Nn);
    k_fill<<<(Ee + 255) / 256, 256>>>(ei);

    for (int i = 0; i < LL; i++) {
        k_hgemm<HH, false><<<ggrid, 256, HGEMM_SMEM>>>(h16, gWT + (size_t)i * HH * HH,
                                                       nullptr, m16, Nn);
        k_agg<<<(Nn + 7) / 8, 256>>>(m16, h16, bnS + i * HH, bnT + i * HH);
    }

    k_pool<<<Gg, 256>>>(h16, batch);
    k_heads<<<dim3((Gg + GPG - 1) / GPG, PP), 128>>>(h1W, h1b, h2W, h2b, h3W, h3b, out);
}

// round 13
// speedup vs baseline: 1.0405x; 1.0405x over previous
#include <cuda_runtime.h>
#include <cuda_fp16.h>
#include <math.h>
#include <stdint.h>

// Problem constants
#define Nn 50000
#define Ee 800000
#define Gg 1000
#define ND 128
#define HH 256
#define LL 4
#define PP 3

// ---------------- static scratch (no allocations allowed) ----------------
__device__ __half g_x16[Nn * ND];
__device__ __half g_h16[Nn * HH];            // hidden state, fp16, updated in place
__device__ __half g_m16[Nn * HH];
__device__ __half g_embWT[HH * ND];          // [n][k] = emb_W[k][n]
__device__ __half g_gcnWT[LL * HH * HH];     // [l][n][k] = gcn_W[l][k][n]
__device__ float  g_bnS[LL * HH];
__device__ float  g_bnT[LL * HH];
__device__ int    g_cnt[Nn];
__device__ int    g_fill[Nn];
__device__ float  g_dinv[Nn];
__device__ int    g_rowptr[Nn + 1];
__device__ int    g_colidx[Ee];
__device__ float  g_ew[Ee];
__device__ float  g_pool[Gg * HH];

// ---------------- graph preprocessing ----------------
__global__ void k_count(const int* __restrict__ ei)
{
    int e = blockIdx.x * blockDim.x + threadIdx.x;
    if (e < Ee) atomicAdd(&g_cnt[ei[Ee + e]], 1);
}

#define SCAN_CH 49   // ceil(50000/1024)
__global__ __launch_bounds__(1024) void k_scan()
{
    __shared__ int wsum[32];
    int t = threadIdx.x;
    int lane = t & 31, wrp = t >> 5;
    int base = t * SCAN_CH;

    int s = 0;
    #pragma unroll 7
    for (int i = 0; i < SCAN_CH; i++) {
        int idx = base + i;
        if (idx < Nn) {
            int c = g_cnt[idx];
            g_dinv[idx] = rsqrtf(1.0f + (float)c);
            s += c;
        }
    }
    int ps = s;
    #pragma unroll
    for (int d = 1; d < 32; d <<= 1) {
        int x = __shfl_up_sync(0xffffffffu, ps, d);
        if (lane >= d) ps += x;
    }
    if (lane == 31) wsum[wrp] = ps;
    __syncthreads();
    if (wrp == 0) {
        int x = wsum[lane];
        #pragma unroll
        for (int d = 1; d < 32; d <<= 1) {
            int y = __shfl_up_sync(0xffffffffu, x, d);
            if (lane >= d) x += y;
        }
        wsum[lane] = x;
    }
    __syncthreads();
    int off = ps - s + (wrp ? wsum[wrp - 1] : 0);

    #pragma unroll 7
    for (int i = 0; i < SCAN_CH; i++) {
        int idx = base + i;
        if (idx < Nn) {
            g_rowptr[idx] = off;
            off += g_cnt[idx];
        }
    }
    if (t == 0) g_rowptr[Nn] = Ee;
}

__global__ void k_fill(const int* __restrict__ ei)
{
    int e = blockIdx.x * blockDim.x + threadIdx.x;
    if (e >= Ee) return;
    int s = ei[e];
    int d = ei[Ee + e];
    int pos = g_rowptr[d] + atomicAdd(&g_fill[d], 1);
    g_colidx[pos] = s;
    g_ew[pos] = g_dinv[s] * g_dinv[d];
}

// ---------------- merged prep: x->fp16, weight transpose+cvt, BN fold ----------------
#define X4 (Nn * ND / 4)
#define WELEMS (HH*ND + LL*HH*HH)
__global__ __launch_bounds__(256) void k_prep(
    const float* __restrict__ x,
    const float* __restrict__ embW, const float* __restrict__ gcnW,
    const float* __restrict__ gcnb, const float* __restrict__ bng,
    const float* __restrict__ bnb, const float* __restrict__ bnm,
    const float* __restrict__ bnv)
{
    int t = blockIdx.x * blockDim.x + threadIdx.x;
    if (t < X4) {
        float4 v = ((const float4*)x)[t];
        __half2 a = __floats2half2_rn(v.x, v.y);
        __half2 b = __floats2half2_rn(v.z, v.w);
        uint2 o;
        o.x = *(uint32_t*)&a;
        o.y = *(uint32_t*)&b;
        ((uint2*)g_x16)[t] = o;
        return;
    }
    int u = t - X4;
    if (u < HH * ND) {
        int n = u / ND, k = u % ND;
        g_embWT[u] = __float2half_rn(embW[k * HH + n]);
    } else if (u < WELEMS) {
        int t2 = u - HH * ND;
        int l = t2 >> 16;
        int r = t2 & 65535;
        int n = r >> 8, k = r & 255;
        g_gcnWT[t2] = __float2half_rn(gcnW[l * HH * HH + k * HH + n]);
    } else if (u < WELEMS + LL * HH) {
        int i = u - WELEMS;
        float S = bng[i] * rsqrtf(bnv[i] + 1e-5f);
        g_bnS[i] = S;
        g_bnT[i] = (gcnb[i] - bnm[i]) * S + bnb[i];
    }
}
#define PREP_ITEMS (X4 + WELEMS + LL*HH)

// ---------------- fp16 tensor-core GEMM: 128x128, 3-stage, ldmatrix ----------------
__device__ __forceinline__ void cpa16(uint32_t dst, const void* src, int sz)
{
    asm volatile("cp.async.cg.shared.global [%0], [%1], 16, %2;\n"
                 :: "r"(dst), "l"(src), "r"(sz));
}
#define CP_COMMIT() asm volatile("cp.async.commit_group;\n" ::)
#define CP_WAIT(N)  asm volatile("cp.async.wait_group %0;\n" :: "n"(N))

__device__ __forceinline__ void ldm_x4(uint32_t& r0, uint32_t& r1,
                                       uint32_t& r2, uint32_t& r3, uint32_t a)
{
    asm volatile("ldmatrix.sync.aligned.m8n8.x4.shared.b16 {%0,%1,%2,%3}, [%4];"
                 : "=r"(r0), "=r"(r1), "=r"(r2), "=r"(r3) : "r"(a));
}
__device__ __forceinline__ void ldm_x2(uint32_t& r0, uint32_t& r1, uint32_t a)
{
    asm volatile("ldmatrix.sync.aligned.m8n8.x2.shared.b16 {%0,%1}, [%2];"
                 : "=r"(r0), "=r"(r1) : "r"(a));
}

#define STAGE_B 10240      // 128 rows * 40 halfs * 2B, per operand per stage
#define HGEMM_SMEM (6 * STAGE_B)

// RB: fuse bias + relu (embed layer); otherwise pure GEMM.
template<int K, bool RB>
__global__ __launch_bounds__(256, 2) void k_hgemm(
    const __half* __restrict__ A, const __half* __restrict__ BT,
    const float* __restrict__ bias, __half* __restrict__ C16, int M)
{
    constexpr int KT = K / 32;
    extern __shared__ __align__(16) __half sm[];

    int tid = threadIdx.x;
    int wid = tid >> 5, lane = tid & 31;
    int wm = wid & 1;
    int wn = wid >> 1;
    int g = lane >> 2;
    int q = lane & 3;
    int rowBase = blockIdx.x * 128;
    int colBase = blockIdx.y * 128;

    uint32_t sA = (uint32_t)__cvta_generic_to_shared(sm);
    uint32_t sB = sA + 3 * STAGE_B;

    int aRow = wm * 64 + (lane & 15);
    int aKof = (lane >> 4) << 3;
    int bRow = wn * 32 + (lane & 7);
    int bKof = ((lane >> 3) & 1) << 3;

    float c[4][4][4];
    #pragma unroll
    for (int i = 0; i < 4; i++)
        #pragma unroll
        for (int j = 0; j < 4; j++)
            #pragma unroll
            for (int r = 0; r < 4; r++) c[i][j][r] = 0.0f;

    int ldrow = tid >> 2;
    int ldc = tid & 3;

    auto stage = [&](int kt, int buf) {
        #pragma unroll
        for (int l = 0; l < 2; l++) {
            int row = ldrow + l * 64;
            int ga = rowBase + row;
            const __half* srcA = A + (size_t)ga * K + kt * 32 + ldc * 8;
            cpa16(sA + buf * STAGE_B + row * 80 + ldc * 16, srcA, (ga < M) ? 16 : 0);
            const __half* srcB = BT + (size_t)(colBase + row) * K + kt * 32 + ldc * 8;
            cpa16(sB + buf * STAGE_B + row * 80 + ldc * 16, srcB, 16);
        }
    };

    stage(0, 0);
    CP_COMMIT();
    if (KT > 1) { stage(1, 1); CP_COMMIT(); }

    for (int kt = 0; kt < KT; kt++) {
        if (kt + 1 < KT) { CP_WAIT(1); } else { CP_WAIT(0); }
        __syncthreads();
        if (kt + 2 < KT) { stage(kt + 2, (kt + 2) % 3); CP_COMMIT(); }

        uint32_t bA = sA + (kt % 3) * STAGE_B;
        uint32_t bB = sB + (kt % 3) * STAGE_B;

        #pragma unroll
        for (int ks = 0; ks < 32; ks += 16) {
            uint32_t a[4][4], b[4][2];
            #pragma unroll
            for (int mt = 0; mt < 4; mt++)
                ldm_x4(a[mt][0], a[mt][1], a[mt][2], a[mt][3],
                       bA + (aRow + mt * 16) * 80 + (ks + aKof) * 2);
            #pragma unroll
            for (int nt = 0; nt < 4; nt++)
                ldm_x2(b[nt][0], b[nt][1],
                       bB + (bRow + nt * 8) * 80 + (ks + bKof) * 2);
            #pragma unroll
            for (int mt = 0; mt < 4; mt++)
                #pragma unroll
                for (int nt = 0; nt < 4; nt++) {
                    asm volatile(
                        "mma.sync.aligned.m16n8k16.row.col.f32.f16.f16.f32 "
                        "{%0,%1,%2,%3}, {%4,%5,%6,%7}, {%8,%9}, {%0,%1,%2,%3};\n"
                        : "+f"(c[mt][nt][0]), "+f"(c[mt][nt][1]),
                          "+f"(c[mt][nt][2]), "+f"(c[mt][nt][3])
                        : "r"(a[mt][0]), "r"(a[mt][1]), "r"(a[mt][2]), "r"(a[mt][3]),
                          "r"(b[nt][0]), "r"(b[nt][1]));
                }
        }
    }

    // epilogue (fp16 output only)
    #pragma unroll
    for (int nt = 0; nt < 4; nt++) {
        int col = colBase + wn * 32 + nt * 8 + 2 * q;
        float b0 = 0.f, b1 = 0.f;
        if (RB) { b0 = bias[col]; b1 = bias[col + 1]; }
        #pragma unroll
        for (int mt = 0; mt < 4; mt++) {
            int r0 = rowBase + wm * 64 + mt * 16 + g;
            float v0 = c[mt][nt][0] + b0;
            float v1 = c[mt][nt][1] + b1;
            float v2 = c[mt][nt][2] + b0;
            float v3 = c[mt][nt][3] + b1;
            if (RB) {
                v0 = fmaxf(v0, 0.f); v1 = fmaxf(v1, 0.f);
                v2 = fmaxf(v2, 0.f); v3 = fmaxf(v3, 0.f);
            }
            if (r0 < M) {
                __half2 h = __floats2half2_rn(v0, v1);
                *(uint32_t*)&C16[(size_t)r0 * HH + col] = *(uint32_t*)&h;
            }
            if (r0 + 8 < M) {
                __half2 h = __floats2half2_rn(v2, v3);
                *(uint32_t*)&C16[(size_t)(r0 + 8) * HH + col] = *(uint32_t*)&h;
            }
        }
    }
}

// ---------------- aggregation: warp/node, fp16 gather, in-place fp16 h (R10) ----------------
__global__ __launch_bounds__(256) void k_agg(
    const __half* __restrict__ m16, __half* __restrict__ h16,
    const float* __restrict__ S, const float* __restrict__ T)
{
    int wid = threadIdx.x >> 5;
    int l = threadIdx.x & 31;
    int node = blockIdx.x * 8 + wid;
    if (node >= Nn) return;

    const uint4* mv = (const uint4*)m16;
    int beg = g_rowptr[node];
    int end = g_rowptr[node + 1];
    float di = g_dinv[node];
    float sn = di * di;

    float acc[8];
    {
        uint4 v = mv[(size_t)node * 32 + l];
        const __half2* h = (const __half2*)&v;
        #pragma unroll
        for (int j = 0; j < 4; j++) {
            float2 f = __half22float2(h[j]);
            acc[2 * j] = f.x * sn;
            acc[2 * j + 1] = f.y * sn;
        }
    }

    for (int e = beg; e < end; e++) {
        int s = __ldg(&g_colidx[e]);
        float w = __ldg(&g_ew[e]);
        uint4 v = mv[(size_t)s * 32 + l];
        const __half2* h = (const __half2*)&v;
        #pragma unroll
        for (int j = 0; j < 4; j++) {
            float2 f = __half22float2(h[j]);
            acc[2 * j] = fmaf(f.x, w, acc[2 * j]);
            acc[2 * j + 1] = fmaf(f.y, w, acc[2 * j + 1]);
        }
    }

    float4 sv0 = ((const float4*)S)[l * 2];
    float4 sv1 = ((const float4*)S)[l * 2 + 1];
    float4 tv0 = ((const float4*)T)[l * 2];
    float4 tv1 = ((const float4*)T)[l * 2 + 1];

    float hi[8];
    {
        uint4 hv = ((const uint4*)h16)[(size_t)node * 32 + l];
        const __half2* h = (const __half2*)&hv;
        #pragma unroll
        for (int j = 0; j < 4; j++) {
            float2 f = __half22float2(h[j]);
            hi[2 * j] = f.x;
            hi[2 * j + 1] = f.y;
        }
    }

    float o[8];
    o[0] = fmaxf(fmaf(acc[0], sv0.x, tv0.x), 0.f) + hi[0];
    o[1] = fmaxf(fmaf(acc[1], sv0.y, tv0.y), 0.f) + hi[1];
    o[2] = fmaxf(fmaf(acc[2], sv0.z, tv0.z), 0.f) + hi[2];
    o[3] = fmaxf(fmaf(acc[3], sv0.w, tv0.w), 0.f) + hi[3];
    o[4] = fmaxf(fmaf(acc[4], sv1.x, tv1.x), 0.f) + hi[4];
    o[5] = fmaxf(fmaf(acc[5], sv1.y, tv1.y), 0.f) + hi[5];
    o[6] = fmaxf(fmaf(acc[6], sv1.z, tv1.z), 0.f) + hi[6];
    o[7] = fmaxf(fmaf(acc[7], sv1.w, tv1.w), 0.f) + hi[7];

    __half2 p0 = __floats2half2_rn(o[0], o[1]);
    __half2 p1 = __floats2half2_rn(o[2], o[3]);
    __half2 p2 = __floats2half2_rn(o[4], o[5]);
    __half2 p3 = __floats2half2_rn(o[6], o[7]);
    uint4 pk;
    pk.x = *(uint32_t*)&p0; pk.y = *(uint32_t*)&p1;
    pk.z = *(uint32_t*)&p2; pk.w = *(uint32_t*)&p3;
    ((uint4*)h16)[(size_t)node * 32 + l] = pk;
}

// ---------------- global mean pool per graph (fp16 h, fp32 accumulate) ----------------
__device__ __forceinline__ int lbound(const int* __restrict__ a, int n, int key)
{
    int lo = 0, hi = n;
    while (lo < hi) {
        int mid = (lo + hi) >> 1;
        if (a[mid] < key) lo = mid + 1; else hi = mid;
    }
    return lo;
}

__global__ __launch_bounds__(256) void k_pool(const __half* __restrict__ h,
                                              const int* __restrict__ batch)
{
    int g = blockIdx.x;
    int c = threadIdx.x;
    int s = lbound(batch, Nn, g);
    int e = lbound(batch, Nn, g + 1);
    float acc = 0.0f;
    for (int n = s; n < e; n++) acc += __half2float(h[(size_t)n * HH + c]);
    float cnt = (float)(e - s);
    g_pool[g * HH + c] = acc / fmaxf(cnt, 1.0f);
}

// ---------------- property-head MLPs: 8 graphs per block (W reuse) ----------------
#define GPG 8
__global__ __launch_bounds__(128) void k_heads(
    const float* __restrict__ h1W, const float* __restrict__ h1b,
    const float* __restrict__ h2W, const float* __restrict__ h2b,
    const float* __restrict__ h3W, const float* __restrict__ h3b,
    float* __restrict__ out)
{
    int gbase = blockIdx.x * GPG;
    int p = blockIdx.y;
    __shared__ float gs[GPG][HH];
    __shared__ float z1[GPG][128];
    __shared__ float z2[GPG][64];
    int t = threadIdx.x;

    for (int i = t; i < GPG * HH; i += 128) {
        int gg = i >> 8, c = i & 255;
        int g = gbase + gg;
        gs[gg][c] = (g < Gg) ? g_pool[g * HH + c] : 0.0f;
    }
    __syncthreads();

    {   // layer 1: 256 -> 128
        const float* W1 = h1W + (size_t)p * HH * 128;
        float acc[GPG];
        #pragma unroll
        for (int gg = 0; gg < GPG; gg++) acc[gg] = h1b[p * 128 + t];
        #pragma unroll 4
        for (int k = 0; k < HH; k++) {
            float w = W1[k * 128 + t];
            #pragma unroll
            for (int gg = 0; gg < GPG; gg++)
                acc[gg] = fmaf(gs[gg][k], w, acc[gg]);
        }
        #pragma unroll
        for (int gg = 0; gg < GPG; gg++) z1[gg][t] = fmaxf(acc[gg], 0.0f);
    }
    __syncthreads();

    if (t < 64) {   // layer 2: 128 -> 64
        const float* W2 = h2W + (size_t)p * 128 * 64;
        float acc[GPG];
        #pragma unroll
        for (int gg = 0; gg < GPG; gg++) acc[gg] = h2b[p * 64 + t];
        #pragma unroll 4
        for (int k = 0; k < 128; k++) {
            float w = W2[k * 64 + t];
            #pragma unroll
            for (int gg = 0; gg < GPG; gg++)
                acc[gg] = fmaf(z1[gg][k], w, acc[gg]);
        }
        #pragma unroll
        for (int gg = 0; gg < GPG; gg++) z2[gg][t] = fmaxf(acc[gg], 0.0f);
    }
    __syncthreads();

    if (t < 32) {   // layer 3: 64 -> 1, warp-reduce per graph
        const float* W3 = h3W + p * 64;
        float w0 = W3[t], w1 = W3[t + 32];
        #pragma unroll
        for (int gg = 0; gg < GPG; gg++) {
            float a3 = z2[gg][t] * w0 + z2[gg][t + 32] * w1;
            #pragma unroll
            for (int o = 16; o > 0; o >>= 1)
                a3 += __shfl_down_sync(0xffffffffu, a3, o);
            if (t == 0 && gbase + gg < Gg)
                out[(gbase + gg) * PP + p] = a3 + h3b[p];
        }
    }
}

// ---------------- launch ----------------
extern "C" void kernel_launch(void* const* d_in, const int* in_sizes, int n_in,
                              void* d_out, int out_size)
{
    const float* x     = (const float*)d_in[0];
    const int*   ei    = (const int*)d_in[1];
    const int*   batch = (const int*)d_in[2];
    const float* embW  = (const float*)d_in[3];
    const float* embb  = (const float*)d_in[4];
    const float* gcnW  = (const float*)d_in[5];
    const float* gcnb  = (const float*)d_in[6];
    const float* bng   = (const float*)d_in[7];
    const float* bnb   = (const float*)d_in[8];
    const float* bnm   = (const float*)d_in[9];
    const float* bnv   = (const float*)d_in[10];
    const float* h1W   = (const float*)d_in[11];
    const float* h1b   = (const float*)d_in[12];
    const float* h2W   = (const float*)d_in[13];
    const float* h2b   = (const float*)d_in[14];
    const float* h3W   = (const float*)d_in[15];
    const float* h3b   = (const float*)d_in[16];
    float* out = (float*)d_out;

    void *pX16_, *pH16_, *pM16_, *pEWT_, *pGWT_, *pS_, *pT_, *pCnt_, *pFill_;
    cudaGetSymbolAddress(&pX16_, g_x16);
    cudaGetSymbolAddress(&pH16_, g_h16);
    cudaGetSymbolAddress(&pM16_, g_m16);
    cudaGetSymbolAddress(&pEWT_, g_embWT);
    cudaGetSymbolAddress(&pGWT_, g_gcnWT);
    cudaGetSymbolAddress(&pS_, g_bnS);
    cudaGetSymbolAddress(&pT_, g_bnT);
    cudaGetSymbolAddress(&pCnt_, g_cnt);
    cudaGetSymbolAddress(&pFill_, g_fill);
    __half* x16 = (__half*)pX16_;
    __half* h16 = (__half*)pH16_;
    __half* m16 = (__half*)pM16_;
    __half* eWT = (__half*)pEWT_;
    __half* gWT = (__half*)pGWT_;
    float*  bnS = (float*)pS_;
    float*  bnT = (float*)pT_;

    cudaFuncSetAttribute(k_hgemm<ND, true>, cudaFuncAttributeMaxDynamicSharedMemorySize, HGEMM_SMEM);
    cudaFuncSetAttribute(k_hgemm<HH, false>, cudaFuncAttributeMaxDynamicSharedMemorySize, HGEMM_SMEM);

    // One-time host-side stream/event setup (no device memory involved).
    static cudaStream_t s2 = nullptr;
    static cudaEvent_t evFork = nullptr, evJoin = nullptr;
    if (s2 == nullptr) {
        cudaStreamCreateWithFlags(&s2, cudaStreamNonBlocking);
        cudaEventCreateWithFlags(&evFork, cudaEventDisableTiming);
        cudaEventCreateWithFlags(&evJoin, cudaEventDisableTiming);
    }

    dim3 ggrid((Nn + 127) / 128, 2);

    // ---- fork: CSR pipeline on s2, compute pipeline on default stream ----
    cudaEventRecord(evFork, 0);
    cudaStreamWaitEvent(s2, evFork, 0);

    // s2 branch: memsets + degree count + scan + fill
    cudaMemsetAsync(pCnt_, 0, Nn * sizeof(int), s2);
    cudaMemsetAsync(pFill_, 0, Nn * sizeof(int), s2);
    k_count<<<(Ee + 255) / 256, 256, 0, s2>>>(ei);
    k_scan<<<1, 1024, 0, s2>>>();
    k_fill<<<(Ee + 255) / 256, 256, 0, s2>>>(ei);
    cudaEventRecord(evJoin, s2);

    // default branch: prep + embed GEMM + layer-0 GEMM (independent of CSR)
    k_prep<<<(PREP_ITEMS + 255) / 256, 256>>>(x, embW, gcnW, gcnb,
                                              bng, bnb, bnm, bnv);
    k_hgemm<ND, true><<<ggrid, 256, HGEMM_SMEM>>>(x16, eWT, embb, h16, Nn);
    k_hgemm<HH, false><<<ggrid, 256, HGEMM_SMEM>>>(h16, gWT, nullptr, m16, Nn);

    // join: agg needs the CSR
    cudaStreamWaitEvent(0, evJoin, 0);
    k_agg<<<(Nn + 7) / 8, 256>>>(m16, h16, bnS, bnT);

    for (int i = 1; i < LL; i++) {
        k_hgemm<HH, false><<<ggrid, 256, HGEMM_SMEM>>>(h16, gWT + (size_t)i * HH * HH,
                                                       nullptr, m16, Nn);
        k_agg<<<(Nn + 7) / 8, 256>>>(m16, h16, bnS + i * HH, bnT + i * HH);
    }

    k_pool<<<Gg, 256>>>(h16, batch);
    k_heads<<<dim3((Gg + GPG - 1) / GPG, PP), 128>>>(h1W, h1b, h2W, h2b, h3W, h3b, out);
}

// round 14
// speedup vs baseline: 1.0415x; 1.0010x over previous
#include <cuda_runtime.h>
#include <cuda_fp16.h>
#include <math.h>
#include <stdint.h>

// Problem constants
#define Nn 50000
#define Ee 800000
#define Gg 1000
#define ND 128
#define HH 256
#define LL 4
#define PP 3

// ---------------- static scratch (no allocations allowed) ----------------
__device__ __half g_x16[Nn * ND];
__device__ __half g_h16[Nn * HH];            // hidden state, fp16, updated in place
__device__ __half g_m16[Nn * HH];
__device__ __half g_embWT[HH * ND];          // [n][k] = emb_W[k][n]
__device__ __half g_gcnWT[LL * HH * HH];     // [l][n][k] = gcn_W[l][k][n]
__device__ float  g_bnS[LL * HH];
__device__ float  g_bnT[LL * HH];
__device__ int    g_cnt[Nn];
__device__ int    g_fill[Nn];
__device__ float  g_dinv[Nn];
__device__ int    g_rowptr[Nn + 1];
__device__ int    g_colidx[Ee];
__device__ float  g_ew[Ee];
__device__ float  g_pool[Gg * HH];

// ---------------- graph preprocessing ----------------
__global__ void k_count(const int* __restrict__ ei)
{
    int e = blockIdx.x * blockDim.x + threadIdx.x;
    if (e < Ee) atomicAdd(&g_cnt[ei[Ee + e]], 1);
}

#define SCAN_CH 49   // ceil(50000/1024)
__global__ __launch_bounds__(1024) void k_scan()
{
    __shared__ int wsum[32];
    int t = threadIdx.x;
    int lane = t & 31, wrp = t >> 5;
    int base = t * SCAN_CH;

    int s = 0;
    #pragma unroll 7
    for (int i = 0; i < SCAN_CH; i++) {
        int idx = base + i;
        if (idx < Nn) {
            int c = g_cnt[idx];
            g_dinv[idx] = rsqrtf(1.0f + (float)c);
            s += c;
        }
    }
    int ps = s;
    #pragma unroll
    for (int d = 1; d < 32; d <<= 1) {
        int x = __shfl_up_sync(0xffffffffu, ps, d);
        if (lane >= d) ps += x;
    }
    if (lane == 31) wsum[wrp] = ps;
    __syncthreads();
    if (wrp == 0) {
        int x = wsum[lane];
        #pragma unroll
        for (int d = 1; d < 32; d <<= 1) {
            int y = __shfl_up_sync(0xffffffffu, x, d);
            if (lane >= d) x += y;
        }
        wsum[lane] = x;
    }
    __syncthreads();
    int off = ps - s + (wrp ? wsum[wrp - 1] : 0);

    #pragma unroll 7
    for (int i = 0; i < SCAN_CH; i++) {
        int idx = base + i;
        if (idx < Nn) {
            g_rowptr[idx] = off;
            off += g_cnt[idx];
        }
    }
    if (t == 0) g_rowptr[Nn] = Ee;
}

__global__ void k_fill(const int* __restrict__ ei)
{
    int e = blockIdx.x * blockDim.x + threadIdx.x;
    if (e >= Ee) return;
    int s = ei[e];
    int d = ei[Ee + e];
    int pos = g_rowptr[d] + atomicAdd(&g_fill[d], 1);
    g_colidx[pos] = s;
    g_ew[pos] = g_dinv[s] * g_dinv[d];
}

// ---------------- merged prep: x->fp16, weight transpose+cvt, BN fold ----------------
#define X4 (Nn * ND / 4)
#define WELEMS (HH*ND + LL*HH*HH)
__global__ __launch_bounds__(256) void k_prep(
    const float* __restrict__ x,
    const float* __restrict__ embW, const float* __restrict__ gcnW,
    const float* __restrict__ gcnb, const float* __restrict__ bng,
    const float* __restrict__ bnb, const float* __restrict__ bnm,
    const float* __restrict__ bnv)
{
    int t = blockIdx.x * blockDim.x + threadIdx.x;
    if (t < X4) {
        float4 v = ((const float4*)x)[t];
        __half2 a = __floats2half2_rn(v.x, v.y);
        __half2 b = __floats2half2_rn(v.z, v.w);
        uint2 o;
        o.x = *(uint32_t*)&a;
        o.y = *(uint32_t*)&b;
        ((uint2*)g_x16)[t] = o;
        return;
    }
    int u = t - X4;
    if (u < HH * ND) {
        int n = u / ND, k = u % ND;
        g_embWT[u] = __float2half_rn(embW[k * HH + n]);
    } else if (u < WELEMS) {
        int t2 = u - HH * ND;
        int l = t2 >> 16;
        int r = t2 & 65535;
        int n = r >> 8, k = r & 255;
        g_gcnWT[t2] = __float2half_rn(gcnW[l * HH * HH + k * HH + n]);
    } else if (u < WELEMS + LL * HH) {
        int i = u - WELEMS;
        float S = bng[i] * rsqrtf(bnv[i] + 1e-5f);
        g_bnS[i] = S;
        g_bnT[i] = (gcnb[i] - bnm[i]) * S + bnb[i];
    }
}
#define PREP_ITEMS (X4 + WELEMS + LL*HH)

// ---------------- fp16 tensor-core GEMM: 128x128, 3-stage, ldmatrix ----------------
__device__ __forceinline__ void cpa16(uint32_t dst, const void* src, int sz)
{
    asm volatile("cp.async.cg.shared.global [%0], [%1], 16, %2;\n"
                 :: "r"(dst), "l"(src), "r"(sz));
}
#define CP_COMMIT() asm volatile("cp.async.commit_group;\n" ::)
#define CP_WAIT(N)  asm volatile("cp.async.wait_group %0;\n" :: "n"(N))

__device__ __forceinline__ void ldm_x4(uint32_t& r0, uint32_t& r1,
                                       uint32_t& r2, uint32_t& r3, uint32_t a)
{
    asm volatile("ldmatrix.sync.aligned.m8n8.x4.shared.b16 {%0,%1,%2,%3}, [%4];"
                 : "=r"(r0), "=r"(r1), "=r"(r2), "=r"(r3) : "r"(a));
}
__device__ __forceinline__ void ldm_x2(uint32_t& r0, uint32_t& r1, uint32_t a)
{
    asm volatile("ldmatrix.sync.aligned.m8n8.x2.shared.b16 {%0,%1}, [%2];"
                 : "=r"(r0), "=r"(r1) : "r"(a));
}

#define STAGE_B 10240      // 128 rows * 40 halfs * 2B, per operand per stage
#define HGEMM_SMEM (6 * STAGE_B)

// RB: fuse bias + relu (embed layer); otherwise pure GEMM.
template<int K, bool RB>
__global__ __launch_bounds__(256, 2) void k_hgemm(
    const __half* __restrict__ A, const __half* __restrict__ BT,
    const float* __restrict__ bias, __half* __restrict__ C16, int M)
{
    constexpr int KT = K / 32;
    extern __shared__ __align__(16) __half sm[];

    int tid = threadIdx.x;
    int wid = tid >> 5, lane = tid & 31;
    int wm = wid & 1;
    int wn = wid >> 1;
    int g = lane >> 2;
    int q = lane & 3;
    int rowBase = blockIdx.x * 128;
    int colBase = blockIdx.y * 128;

    uint32_t sA = (uint32_t)__cvta_generic_to_shared(sm);
    uint32_t sB = sA + 3 * STAGE_B;

    int aRow = wm * 64 + (lane & 15);
    int aKof = (lane >> 4) << 3;
    int bRow = wn * 32 + (lane & 7);
    int bKof = ((lane >> 3) & 1) << 3;

    float c[4][4][4];
    #pragma unroll
    for (int i = 0; i < 4; i++)
        #pragma unroll
        for (int j = 0; j < 4; j++)
            #pragma unroll
            for (int r = 0; r < 4; r++) c[i][j][r] = 0.0f;

    int ldrow = tid >> 2;
    int ldc = tid & 3;

    auto stage = [&](int kt, int buf) {
        #pragma unroll
        for (int l = 0; l < 2; l++) {
            int row = ldrow + l * 64;
            int ga = rowBase + row;
            const __half* srcA = A + (size_t)ga * K + kt * 32 + ldc * 8;
            cpa16(sA + buf * STAGE_B + row * 80 + ldc * 16, srcA, (ga < M) ? 16 : 0);
            const __half* srcB = BT + (size_t)(colBase + row) * K + kt * 32 + ldc * 8;
            cpa16(sB + buf * STAGE_B + row * 80 + ldc * 16, srcB, 16);
        }
    };

    stage(0, 0);
    CP_COMMIT();
    if (KT > 1) { stage(1, 1); CP_COMMIT(); }

    for (int kt = 0; kt < KT; kt++) {
        if (kt + 1 < KT) { CP_WAIT(1); } else { CP_WAIT(0); }
        __syncthreads();
        if (kt + 2 < KT) { stage(kt + 2, (kt + 2) % 3); CP_COMMIT(); }

        uint32_t bA = sA + (kt % 3) * STAGE_B;
        uint32_t bB = sB + (kt % 3) * STAGE_B;

        #pragma unroll
        for (int ks = 0; ks < 32; ks += 16) {
            uint32_t a[4][4], b[4][2];
            #pragma unroll
            for (int mt = 0; mt < 4; mt++)
                ldm_x4(a[mt][0], a[mt][1], a[mt][2], a[mt][3],
                       bA + (aRow + mt * 16) * 80 + (ks + aKof) * 2);
            #pragma unroll
            for (int nt = 0; nt < 4; nt++)
                ldm_x2(b[nt][0], b[nt][1],
                       bB + (bRow + nt * 8) * 80 + (ks + bKof) * 2);
            #pragma unroll
            for (int mt = 0; mt < 4; mt++)
                #pragma unroll
                for (int nt = 0; nt < 4; nt++) {
                    asm volatile(
                        "mma.sync.aligned.m16n8k16.row.col.f32.f16.f16.f32 "
                        "{%0,%1,%2,%3}, {%4,%5,%6,%7}, {%8,%9}, {%0,%1,%2,%3};\n"
                        : "+f"(c[mt][nt][0]), "+f"(c[mt][nt][1]),
                          "+f"(c[mt][nt][2]), "+f"(c[mt][nt][3])
                        : "r"(a[mt][0]), "r"(a[mt][1]), "r"(a[mt][2]), "r"(a[mt][3]),
                          "r"(b[nt][0]), "r"(b[nt][1]));
                }
        }
    }

    // epilogue (fp16 output only)
    #pragma unroll
    for (int nt = 0; nt < 4; nt++) {
        int col = colBase + wn * 32 + nt * 8 + 2 * q;
        float b0 = 0.f, b1 = 0.f;
        if (RB) { b0 = bias[col]; b1 = bias[col + 1]; }
        #pragma unroll
        for (int mt = 0; mt < 4; mt++) {
            int r0 = rowBase + wm * 64 + mt * 16 + g;
            float v0 = c[mt][nt][0] + b0;
            float v1 = c[mt][nt][1] + b1;
            float v2 = c[mt][nt][2] + b0;
            float v3 = c[mt][nt][3] + b1;
            if (RB) {
                v0 = fmaxf(v0, 0.f); v1 = fmaxf(v1, 0.f);
                v2 = fmaxf(v2, 0.f); v3 = fmaxf(v3, 0.f);
            }
            if (r0 < M) {
                __half2 h = __floats2half2_rn(v0, v1);
                *(uint32_t*)&C16[(size_t)r0 * HH + col] = *(uint32_t*)&h;
            }
            if (r0 + 8 < M) {
                __half2 h = __floats2half2_rn(v2, v3);
                *(uint32_t*)&C16[(size_t)(r0 + 8) * HH + col] = *(uint32_t*)&h;
            }
        }
    }
}

// ---------------- aggregation: warp/node, fp16 gather, in-place fp16 h (R10) ----------------
__global__ __launch_bounds__(256) void k_agg(
    const __half* __restrict__ m16, __half* __restrict__ h16,
    const float* __restrict__ S, const float* __restrict__ T)
{
    int wid = threadIdx.x >> 5;
    int l = threadIdx.x & 31;
    int node = blockIdx.x * 8 + wid;
    if (node >= Nn) return;

    const uint4* mv = (const uint4*)m16;
    int beg = g_rowptr[node];
    int end = g_rowptr[node + 1];
    float di = g_dinv[node];
    float sn = di * di;

    float acc[8];
    {
        uint4 v = mv[(size_t)node * 32 + l];
        const __half2* h = (const __half2*)&v;
        #pragma unroll
        for (int j = 0; j < 4; j++) {
            float2 f = __half22float2(h[j]);
            acc[2 * j] = f.x * sn;
            acc[2 * j + 1] = f.y * sn;
        }
    }

    for (int e = beg; e < end; e++) {
        int s = __ldg(&g_colidx[e]);
        float w = __ldg(&g_ew[e]);
        uint4 v = mv[(size_t)s * 32 + l];
        const __half2* h = (const __half2*)&v;
        #pragma unroll
        for (int j = 0; j < 4; j++) {
            float2 f = __half22float2(h[j]);
            acc[2 * j] = fmaf(f.x, w, acc[2 * j]);
            acc[2 * j + 1] = fmaf(f.y, w, acc[2 * j + 1]);
        }
    }

    float4 sv0 = ((const float4*)S)[l * 2];
    float4 sv1 = ((const float4*)S)[l * 2 + 1];
    float4 tv0 = ((const float4*)T)[l * 2];
    float4 tv1 = ((const float4*)T)[l * 2 + 1];

    float hi[8];
    {
        uint4 hv = ((const uint4*)h16)[(size_t)node * 32 + l];
        const __half2* h = (const __half2*)&hv;
        #pragma unroll
        for (int j = 0; j < 4; j++) {
            float2 f = __half22float2(h[j]);
            hi[2 * j] = f.x;
            hi[2 * j + 1] = f.y;
        }
    }

    float o[8];
    o[0] = fmaxf(fmaf(acc[0], sv0.x, tv0.x), 0.f) + hi[0];
    o[1] = fmaxf(fmaf(acc[1], sv0.y, tv0.y), 0.f) + hi[1];
    o[2] = fmaxf(fmaf(acc[2], sv0.z, tv0.z), 0.f) + hi[2];
    o[3] = fmaxf(fmaf(acc[3], sv0.w, tv0.w), 0.f) + hi[3];
    o[4] = fmaxf(fmaf(acc[4], sv1.x, tv1.x), 0.f) + hi[4];
    o[5] = fmaxf(fmaf(acc[5], sv1.y, tv1.y), 0.f) + hi[5];
    o[6] = fmaxf(fmaf(acc[6], sv1.z, tv1.z), 0.f) + hi[6];
    o[7] = fmaxf(fmaf(acc[7], sv1.w, tv1.w), 0.f) + hi[7];

    __half2 p0 = __floats2half2_rn(o[0], o[1]);
    __half2 p1 = __floats2half2_rn(o[2], o[3]);
    __half2 p2 = __floats2half2_rn(o[4], o[5]);
    __half2 p3 = __floats2half2_rn(o[6], o[7]);
    uint4 pk;
    pk.x = *(uint32_t*)&p0; pk.y = *(uint32_t*)&p1;
    pk.z = *(uint32_t*)&p2; pk.w = *(uint32_t*)&p3;
    ((uint4*)h16)[(size_t)node * 32 + l] = pk;
}

// ---------------- global mean pool per graph (fp16 h, fp32 accumulate) ----------------
__device__ __forceinline__ int lbound(const int* __restrict__ a, int n, int key)
{
    int lo = 0, hi = n;
    while (lo < hi) {
        int mid = (lo + hi) >> 1;
        if (a[mid] < key) lo = mid + 1; else hi = mid;
    }
    return lo;
}

__global__ __launch_bounds__(256) void k_pool(const __half* __restrict__ h,
                                              const int* __restrict__ batch)
{
    int g = blockIdx.x;
    int c = threadIdx.x;
    int s = lbound(batch, Nn, g);
    int e = lbound(batch, Nn, g + 1);
    float acc = 0.0f;
    for (int n = s; n < e; n++) acc += __half2float(h[(size_t)n * HH + c]);
    float cnt = (float)(e - s);
    g_pool[g * HH + c] = acc / fmaxf(cnt, 1.0f);
}

// ---------------- property-head MLPs: 8 graphs per block (W reuse) ----------------
#define GPG 8
__global__ __launch_bounds__(128) void k_heads(
    const float* __restrict__ h1W, const float* __restrict__ h1b,
    const float* __restrict__ h2W, const float* __restrict__ h2b,
    const float* __restrict__ h3W, const float* __restrict__ h3b,
    float* __restrict__ out)
{
    int gbase = blockIdx.x * GPG;
    int p = blockIdx.y;
    __shared__ float gs[GPG][HH];
    __shared__ float z1[GPG][128];
    __shared__ float z2[GPG][64];
    int t = threadIdx.x;

    for (int i = t; i < GPG * HH; i += 128) {
        int gg = i >> 8, c = i & 255;
        int g = gbase + gg;
        gs[gg][c] = (g < Gg) ? g_pool[g * HH + c] : 0.0f;
    }
    __syncthreads();

    {   // layer 1: 256 -> 128
        const float* W1 = h1W + (size_t)p * HH * 128;
        float acc[GPG];
        #pragma unroll
        for (int gg = 0; gg < GPG; gg++) acc[gg] = h1b[p * 128 + t];
        #pragma unroll 4
        for (int k = 0; k < HH; k++) {
            float w = W1[k * 128 + t];
            #pragma unroll
            for (int gg = 0; gg < GPG; gg++)
                acc[gg] = fmaf(gs[gg][k], w, acc[gg]);
        }
        #pragma unroll
        for (int gg = 0; gg < GPG; gg++) z1[gg][t] = fmaxf(acc[gg], 0.0f);
    }
    __syncthreads();

    if (t < 64) {   // layer 2: 128 -> 64
        const float* W2 = h2W + (size_t)p * 128 * 64;
        float acc[GPG];
        #pragma unroll
        for (int gg = 0; gg < GPG; gg++) acc[gg] = h2b[p * 64 + t];
        #pragma unroll 4
        for (int k = 0; k < 128; k++) {
            float w = W2[k * 64 + t];
            #pragma unroll
            for (int gg = 0; gg < GPG; gg++)
                acc[gg] = fmaf(z1[gg][k], w, acc[gg]);
        }
        #pragma unroll
        for (int gg = 0; gg < GPG; gg++) z2[gg][t] = fmaxf(acc[gg], 0.0f);
    }
    __syncthreads();

    if (t < 32) {   // layer 3: 64 -> 1, warp-reduce per graph
        const float* W3 = h3W + p * 64;
        float w0 = W3[t], w1 = W3[t + 32];
        #pragma unroll
        for (int gg = 0; gg < GPG; gg++) {
            float a3 = z2[gg][t] * w0 + z2[gg][t + 32] * w1;
            #pragma unroll
            for (int o = 16; o > 0; o >>= 1)
                a3 += __shfl_down_sync(0xffffffffu, a3, o);
            if (t == 0 && gbase + gg < Gg)
                out[(gbase + gg) * PP + p] = a3 + h3b[p];
        }
    }
}

// ---------------- launch ----------------
extern "C" void kernel_launch(void* const* d_in, const int* in_sizes, int n_in,
                              void* d_out, int out_size)
{
    const float* x     = (const float*)d_in[0];
    const int*   ei    = (const int*)d_in[1];
    const int*   batch = (const int*)d_in[2];
    const float* embW  = (const float*)d_in[3];
    const float* embb  = (const float*)d_in[4];
    const float* gcnW  = (const float*)d_in[5];
    const float* gcnb  = (const float*)d_in[6];
    const float* bng   = (const float*)d_in[7];
    const float* bnb   = (const float*)d_in[8];
    const float* bnm   = (const float*)d_in[9];
    const float* bnv   = (const float*)d_in[10];
    const float* h1W   = (const float*)d_in[11];
    const float* h1b   = (const float*)d_in[12];
    const float* h2W   = (const float*)d_in[13];
    const float* h2b   = (const float*)d_in[14];
    const float* h3W   = (const float*)d_in[15];
    const float* h3b   = (const float*)d_in[16];
    float* out = (float*)d_out;

    void *pX16_, *pH16_, *pM16_, *pEWT_, *pGWT_, *pS_, *pT_, *pCnt_, *pFill_;
    cudaGetSymbolAddress(&pX16_, g_x16);
    cudaGetSymbolAddress(&pH16_, g_h16);
    cudaGetSymbolAddress(&pM16_, g_m16);
    cudaGetSymbolAddress(&pEWT_, g_embWT);
    cudaGetSymbolAddress(&pGWT_, g_gcnWT);
    cudaGetSymbolAddress(&pS_, g_bnS);
    cudaGetSymbolAddress(&pT_, g_bnT);
    cudaGetSymbolAddress(&pCnt_, g_cnt);
    cudaGetSymbolAddress(&pFill_, g_fill);
    __half* x16 = (__half*)pX16_;
    __half* h16 = (__half*)pH16_;
    __half* m16 = (__half*)pM16_;
    __half* eWT = (__half*)pEWT_;
    __half* gWT = (__half*)pGWT_;
    float*  bnS = (float*)pS_;
    float*  bnT = (float*)pT_;

    cudaFuncSetAttribute(k_hgemm<ND, true>, cudaFuncAttributeMaxDynamicSharedMemorySize, HGEMM_SMEM);
    cudaFuncSetAttribute(k_hgemm<HH, false>, cudaFuncAttributeMaxDynamicSharedMemorySize, HGEMM_SMEM);

    // One-time host-side stream/event setup (no device memory involved).
    static cudaStream_t s2 = nullptr;
    static cudaEvent_t evFork = nullptr, evJoin = nullptr;
    if (s2 == nullptr) {
        cudaStreamCreateWithFlags(&s2, cudaStreamNonBlocking);
        cudaEventCreateWithFlags(&evFork, cudaEventDisableTiming);
        cudaEventCreateWithFlags(&evJoin, cudaEventDisableTiming);
    }

    dim3 ggrid((Nn + 127) / 128, 2);

    // ---- fork: CSR pipeline on s2, compute pipeline on default stream ----
    cudaEventRecord(evFork, 0);
    cudaStreamWaitEvent(s2, evFork, 0);

    // s2 branch: memsets + degree count + scan + fill
    cudaMemsetAsync(pCnt_, 0, Nn * sizeof(int), s2);
    cudaMemsetAsync(pFill_, 0, Nn * sizeof(int), s2);
    k_count<<<(Ee + 255) / 256, 256, 0, s2>>>(ei);
    k_scan<<<1, 1024, 0, s2>>>();
    k_fill<<<(Ee + 255) / 256, 256, 0, s2>>>(ei);
    cudaEventRecord(evJoin, s2);

    // default branch: prep + embed GEMM + layer-0 GEMM (independent of CSR)
    k_prep<<<(PREP_ITEMS + 255) / 256, 256>>>(x, embW, gcnW, gcnb,
                                              bng, bnb, bnm, bnv);
    k_hgemm<ND, true><<<ggrid, 256, HGEMM_SMEM>>>(x16, eWT, embb, h16, Nn);
    k_hgemm<HH, false><<<ggrid, 256, HGEMM_SMEM>>>(h16, gWT, nullptr, m16, Nn);

    // join: agg needs the CSR
    cudaStreamWaitEvent(0, evJoin, 0);
    k_agg<<<(Nn + 7) / 8, 256>>>(m16, h16, bnS, bnT);

    for (int i = 1; i < LL; i++) {
        k_hgemm<HH, false><<<ggrid, 256, HGEMM_SMEM>>>(h16, gWT + (size_t)i * HH * HH,
                                                       nullptr, m16, Nn);
        k_agg<<<(Nn + 7) / 8, 256>>>(m16, h16, bnS + i * HH, bnT + i * HH);
    }

    k_pool<<<Gg, 256>>>(h16, batch);
    k_heads<<<dim3((Gg + GPG - 1) / GPG, PP), 128>>>(h1W, h1b, h2W, h2b, h3W, h3b, out);
}